// round 16
// baseline (speedup 1.0000x reference)
#include <cuda_runtime.h>
#include <cuda_fp16.h>
#include <cstdint>

#define BATCH  2
#define SEQ    2048
#define DMODEL 1024
#define NHEAD  16
#define HDIM   64
#define MROWS  (BATCH * SEQ)       // 4096

// ---------------------------------------------------------------------------
// Scratch (allocation-free rule: __device__ globals)
// ---------------------------------------------------------------------------
__device__ __half g_xf[MROWS * DMODEL];       // x single fp16
__device__ __half g_wf[4][DMODEL * DMODEL];   // wq,wk,wv,wo single fp16
__device__ __half g_qf[MROWS * DMODEL];       // q single fp16 [bh][s][hd], scaled 0.125
__device__ __half g_kf[MROWS * DMODEL];       // k single fp16 [bh][s][hd]
__device__ __half g_vf[MROWS * DMODEL];       // v single fp16 TRANSPOSED [bh][hd][s]
__device__ __half g_cf[MROWS * DMODEL];       // ctx single fp16 [b*s][d]

// ---------------------------------------------------------------------------
// Warp-MMA + cp.async helpers (base compute_103 PTX)
// ---------------------------------------------------------------------------
__device__ __forceinline__ uint32_t smem_u32(const void* p) {
    uint32_t a;
    asm("{ .reg .u64 t; cvta.to.shared.u64 t, %1; cvt.u32.u64 %0, t; }"
        : "=r"(a) : "l"(p));
    return a;
}

__device__ __forceinline__ void ldmatrix_x4(uint32_t* r, uint32_t addr) {
    asm volatile("ldmatrix.sync.aligned.m8n8.x4.shared.b16 {%0,%1,%2,%3}, [%4];"
                 : "=r"(r[0]), "=r"(r[1]), "=r"(r[2]), "=r"(r[3]) : "r"(addr));
}

__device__ __forceinline__ void mma_f16(float* c, const uint32_t* a, const uint32_t* b) {
    asm volatile(
        "mma.sync.aligned.m16n8k16.row.col.f32.f16.f16.f32 "
        "{%0,%1,%2,%3}, {%4,%5,%6,%7}, {%8,%9}, {%0,%1,%2,%3};"
        : "+f"(c[0]), "+f"(c[1]), "+f"(c[2]), "+f"(c[3])
        : "r"(a[0]), "r"(a[1]), "r"(a[2]), "r"(a[3]), "r"(b[0]), "r"(b[1]));
}

__device__ __forceinline__ void cp_async16(uint32_t dst, const void* src) {
    asm volatile("cp.async.cg.shared.global [%0], [%1], 16;" :: "r"(dst), "l"(src));
}
#define CP_COMMIT() asm volatile("cp.async.commit_group;" ::: "memory")
#define CP_WAIT0()  asm volatile("cp.async.wait_group 0;" ::: "memory")
#define CP_WAIT1()  asm volatile("cp.async.wait_group 1;" ::: "memory")
#define CP_WAIT2()  asm volatile("cp.async.wait_group 2;" ::: "memory")

// ---------------------------------------------------------------------------
// Prep: convert x and the 4 weight matrices to single fp16.
// blocks [0,4096) -> x ; [4096,8192) -> weights (1024 blocks each).
// ---------------------------------------------------------------------------
__global__ __launch_bounds__(256)
void prep_kernel(const float* __restrict__ x,
                 const float* __restrict__ wq, const float* __restrict__ wk,
                 const float* __restrict__ wv, const float* __restrict__ wo,
                 __half* __restrict__ xf, __half* __restrict__ wf)
{
    const int bid = blockIdx.x;
    const float* src;
    __half* dst;
    int i4;
    if (bid < 4096) {
        src = x;
        dst = xf;
        i4 = (bid * 256 + threadIdx.x) * 4;
    } else {
        const int idx = bid - 4096;
        const int wi  = idx >> 10;
        src = (wi == 0) ? wq : (wi == 1) ? wk : (wi == 2) ? wv : wo;
        dst = wf + (size_t)wi * DMODEL * DMODEL;
        i4 = ((idx & 1023) * 256 + threadIdx.x) * 4;
    }
    float4 f = *reinterpret_cast<const float4*>(src + i4);
    *reinterpret_cast<__half2*>(dst + i4)     = __halves2half2(__float2half(f.x), __float2half(f.y));
    *reinterpret_cast<__half2*>(dst + i4 + 2) = __halves2half2(__float2half(f.z), __float2half(f.w));
}

// ---------------------------------------------------------------------------
// GEMM tiling constants
// CTA 128x128 tile, 256 threads / 8 warps (2x4), warp tile 64x32,
// K-chunk 64. 4-stage fully-unrolled pipeline (prefetch distance 3).
// ---------------------------------------------------------------------------
#define LDT       72
#define TILE_ELEM (128 * LDT)
#define TILE_B    (TILE_ELEM * 2)          // 18432 bytes
#define STAGE_B   (2 * TILE_B)             // 36864 bytes
#define NSTAGE    4
#define GEMM_SMEM (NSTAGE * STAGE_B)       // 147456 bytes
#define NCHUNK    (DMODEL / 64)            // 16

// ---------------------------------------------------------------------------
// Merged QKV GEMM: grid (24, 32); which = blockIdx.x>>3 selects wq/wk/wv.
// which 0 -> q [bh][s][hd] scaled 0.125; 1 -> k [bh][s][hd]; 2 -> v^T [bh][hd][s]
// ---------------------------------------------------------------------------
__global__ __launch_bounds__(256)
void mma_gemm_qkv(const __half* __restrict__ xf,
                  const __half* __restrict__ wf,
                  const float* __restrict__ bq,
                  const float* __restrict__ bk,
                  const float* __restrict__ bv,
                  __half* __restrict__ qf,
                  __half* __restrict__ kf,
                  __half* __restrict__ vf)
{
    extern __shared__ __align__(16) char smem[];
    const uint32_t sbase = smem_u32(smem);

    const int tid  = threadIdx.x;
    const int wid  = tid >> 5;
    const int lane = tid & 31;
    const int which = blockIdx.x >> 3;
    const int nBase = (blockIdx.x & 7) * 128;
    const int mBase = blockIdx.y * 128;
    const int warp_m = (wid >> 2) * 64;
    const int warp_n = (wid & 3) * 32;

    const size_t NW = (size_t)DMODEL * DMODEL;
    const __half* W = wf + which * NW;
    const float* bias = (which == 0) ? bq : (which == 1) ? bk : bv;
    const float scale = (which == 0) ? 0.125f : 1.0f;

    auto stage = [&](uint32_t sdst, int kc) {
        #pragma unroll
        for (int t = 0; t < 2; t++) {
            const __half* src = (t == 0) ? xf : W;
            const int rb = (t == 0) ? mBase : nBase;
            #pragma unroll
            for (int it = 0; it < 4; it++) {
                const int slot = tid + it * 256;
                const int row  = slot >> 3;
                const int c8   = slot & 7;
                cp_async16(sdst + t * TILE_B + 2 * (uint32_t)(row * LDT + c8 * 8),
                           src + (size_t)(rb + row) * DMODEL + kc + c8 * 8);
            }
        }
    };

    float acc[4][4][4];
    #pragma unroll
    for (int mi = 0; mi < 4; mi++)
        #pragma unroll
        for (int ni = 0; ni < 4; ni++)
            #pragma unroll
            for (int e = 0; e < 4; e++) acc[mi][ni][e] = 0.0f;

    const uint32_t aRow = (uint32_t)(warp_m + (lane & 15)) * LDT + (lane >> 4) * 8;
    const uint32_t bRow = (uint32_t)(warp_n + 8 * (lane >> 4) + (lane & 7)) * LDT
                          + 8 * ((lane >> 3) & 1);

    // Prologue: 3 stages in flight (groups 0,1,2)
    stage(sbase, 0);
    CP_COMMIT();
    stage(sbase + STAGE_B, 64);
    CP_COMMIT();
    stage(sbase + 2 * STAGE_B, 128);
    CP_COMMIT();

    #pragma unroll
    for (int it = 0; it < NCHUNK; it++) {
        // Before iter it, committed groups reach min(it+2, NCHUNK-1).
        // Group it done after leaving <= min(it+2,NCHUNK-1)-it pending.
        if (it < NCHUNK - 2)      CP_WAIT2();
        else if (it == NCHUNK - 2) CP_WAIT1();
        else                       CP_WAIT0();
        __syncthreads();
        if (it + 3 < NCHUNK) {
            // Buffer (it+3)%4 == (it-1)%4: its readers finished before this barrier.
            stage(sbase + (uint32_t)(((it + 3) % NSTAGE) * STAGE_B), (it + 3) * 64);
            CP_COMMIT();
        }

        const uint32_t sOff = (uint32_t)((it % NSTAGE) * STAGE_B);   // literal after unroll
        const uint32_t uA = sbase + sOff + 2 * aRow;
        const uint32_t uB = sbase + sOff + TILE_B + 2 * bRow;

        #pragma unroll
        for (int ks = 0; ks < 4; ks++) {
            const uint32_t kOff = 2 * (uint32_t)(ks * 16);
            uint32_t a4[4][4], w4[2][4];
            #pragma unroll
            for (int mi = 0; mi < 4; mi++)
                ldmatrix_x4(a4[mi], uA + kOff + 2 * (uint32_t)(mi * 16) * LDT);
            #pragma unroll
            for (int np = 0; np < 2; np++)
                ldmatrix_x4(w4[np], uB + kOff + 2 * (uint32_t)(np * 16) * LDT);
            #pragma unroll
            for (int mi = 0; mi < 4; mi++)
                #pragma unroll
                for (int ni = 0; ni < 4; ni++)
                    mma_f16(acc[mi][ni], a4[mi], &w4[ni >> 1][2 * (ni & 1)]);
        }
    }

    const int rBase = mBase + warp_m + (lane >> 2);
    const int cBase = nBase + warp_n + (lane & 3) * 2;
    #pragma unroll
    for (int mi = 0; mi < 4; mi++) {
        #pragma unroll
        for (int ni = 0; ni < 4; ni++) {
            #pragma unroll
            for (int half = 0; half < 2; half++) {
                const int m = rBase + mi * 16 + half * 8;
                const int n = cBase + ni * 8;
                const float v0 = (acc[mi][ni][half * 2]     + bias[n])     * scale;
                const float v1 = (acc[mi][ni][half * 2 + 1] + bias[n + 1]) * scale;
                const int b  = m >> 11;
                const int s  = m & 2047;
                const int h  = n >> 6;
                const int hd = n & 63;
                if (which < 2) {
                    const size_t idx = (((size_t)(b * NHEAD + h) * SEQ) + s) * HDIM + hd;
                    __half* dst = (which == 0) ? qf : kf;
                    *reinterpret_cast<__half2*>(dst + idx) =
                        __halves2half2(__float2half(v0), __float2half(v1));
                } else {
                    const size_t idx = (((size_t)(b * NHEAD + h) * HDIM) + hd) * SEQ + s;
                    vf[idx]       = __float2half(v0);
                    vf[idx + SEQ] = __float2half(v1);
                }
            }
        }
    }
}

// ---------------------------------------------------------------------------
// Output-projection GEMM (fp32 out), plain fp16, 4-stage unrolled pipeline.
// ---------------------------------------------------------------------------
__global__ __launch_bounds__(256)
void mma_gemm_out(const __half* __restrict__ A,
                  const __half* __restrict__ W,
                  const float* __restrict__ bias,
                  float* __restrict__ out)
{
    extern __shared__ __align__(16) char smem[];
    const uint32_t sbase = smem_u32(smem);

    const int tid  = threadIdx.x;
    const int wid  = tid >> 5;
    const int lane = tid & 31;
    const int mBase = blockIdx.y * 128;
    const int nBase = blockIdx.x * 128;
    const int warp_m = (wid >> 2) * 64;
    const int warp_n = (wid & 3) * 32;

    auto stage = [&](uint32_t sdst, int kc) {
        #pragma unroll
        for (int t = 0; t < 2; t++) {
            const __half* src = (t == 0) ? A : W;
            const int rb = (t == 0) ? mBase : nBase;
            #pragma unroll
            for (int it = 0; it < 4; it++) {
                const int slot = tid + it * 256;
                const int row  = slot >> 3;
                const int c8   = slot & 7;
                cp_async16(sdst + t * TILE_B + 2 * (uint32_t)(row * LDT + c8 * 8),
                           src + (size_t)(rb + row) * DMODEL + kc + c8 * 8);
            }
        }
    };

    float acc[4][4][4];
    #pragma unroll
    for (int mi = 0; mi < 4; mi++)
        #pragma unroll
        for (int ni = 0; ni < 4; ni++)
            #pragma unroll
            for (int e = 0; e < 4; e++) acc[mi][ni][e] = 0.0f;

    const uint32_t aRow = (uint32_t)(warp_m + (lane & 15)) * LDT + (lane >> 4) * 8;
    const uint32_t bRow = (uint32_t)(warp_n + 8 * (lane >> 4) + (lane & 7)) * LDT
                          + 8 * ((lane >> 3) & 1);

    stage(sbase, 0);
    CP_COMMIT();
    stage(sbase + STAGE_B, 64);
    CP_COMMIT();
    stage(sbase + 2 * STAGE_B, 128);
    CP_COMMIT();

    #pragma unroll
    for (int it = 0; it < NCHUNK; it++) {
        if (it < NCHUNK - 2)      CP_WAIT2();
        else if (it == NCHUNK - 2) CP_WAIT1();
        else                       CP_WAIT0();
        __syncthreads();
        if (it + 3 < NCHUNK) {
            stage(sbase + (uint32_t)(((it + 3) % NSTAGE) * STAGE_B), (it + 3) * 64);
            CP_COMMIT();
        }

        const uint32_t sOff = (uint32_t)((it % NSTAGE) * STAGE_B);
        const uint32_t uA = sbase + sOff + 2 * aRow;
        const uint32_t uB = sbase + sOff + TILE_B + 2 * bRow;

        #pragma unroll
        for (int ks = 0; ks < 4; ks++) {
            const uint32_t kOff = 2 * (uint32_t)(ks * 16);
            uint32_t a4[4][4], w4[2][4];
            #pragma unroll
            for (int mi = 0; mi < 4; mi++)
                ldmatrix_x4(a4[mi], uA + kOff + 2 * (uint32_t)(mi * 16) * LDT);
            #pragma unroll
            for (int np = 0; np < 2; np++)
                ldmatrix_x4(w4[np], uB + kOff + 2 * (uint32_t)(np * 16) * LDT);
            #pragma unroll
            for (int mi = 0; mi < 4; mi++)
                #pragma unroll
                for (int ni = 0; ni < 4; ni++)
                    mma_f16(acc[mi][ni], a4[mi], &w4[ni >> 1][2 * (ni & 1)]);
        }
    }

    const int rBase = mBase + warp_m + (lane >> 2);
    const int cBase = nBase + warp_n + (lane & 3) * 2;
    #pragma unroll
    for (int mi = 0; mi < 4; mi++) {
        #pragma unroll
        for (int ni = 0; ni < 4; ni++) {
            #pragma unroll
            for (int half = 0; half < 2; half++) {
                const int m = rBase + mi * 16 + half * 8;
                const int n = cBase + ni * 8;
                out[(size_t)m * DMODEL + n]     = acc[mi][ni][half * 2]     + bias[n];
                out[(size_t)m * DMODEL + n + 1] = acc[mi][ni][half * 2 + 1] + bias[n + 1];
            }
        }
    }
}

// ---------------------------------------------------------------------------
// Tensor-core flash attention (causal), all-single fp16 operands, fp32 softmax.
// q-tile 128 rows, 256 threads (8 warps), k-tile 64, cp.async double-buffered.
// (unchanged from R15)
// ---------------------------------------------------------------------------
#define ALDT   72
#define KT_B   9216
#define AST_B  (2 * KT_B)                  // 18432
#define P_OFF  (2 * AST_B)                 // 36864
#define PT_B   (128 * ALDT * 2)            // 18432
#define ATTN_SMEM (P_OFF + PT_B)           // 55296

__global__ __launch_bounds__(256)
void attn_mma_kernel()
{
    extern __shared__ __align__(16) char asmem[];
    const uint32_t abase = smem_u32(asmem);

    const int tid  = threadIdx.x;
    const int w    = tid >> 5;
    const int lane = tid & 31;
    const int qi   = gridDim.x - 1 - blockIdx.x;
    const int bh   = blockIdx.y;
    const int qBase = qi * 128;
    const int nkt  = 2 * qi + 2;
    const size_t hOff = (size_t)bh * SEQ * HDIM;
    const size_t vOff = (size_t)bh * HDIM * SEQ;

    auto stageKV = [&](uint32_t su, int kBase) {
        #pragma unroll
        for (int it = 0; it < 2; it++) {
            const int slot = tid + it * 256;
            const int row = slot >> 3, c8 = slot & 7;
            const uint32_t so = 2 * (uint32_t)(row * ALDT + c8 * 8);
            cp_async16(su + so,        g_kf + hOff + (size_t)(kBase + row) * HDIM + c8 * 8);
            cp_async16(su + KT_B + so, g_vf + vOff + (size_t)row * SEQ + kBase + c8 * 8);
        }
    };

    stageKV(abase, 0);
    CP_COMMIT();

    {
        __half* sP = reinterpret_cast<__half*>(asmem + P_OFF);
        #pragma unroll
        for (int it = 0; it < 4; it++) {
            const int slot = tid + it * 256;
            const int row = slot >> 3, c8 = slot & 7;
            *reinterpret_cast<uint4*>(sP + row * ALDT + c8 * 8) =
                *reinterpret_cast<const uint4*>(g_qf + hOff + (size_t)(qBase + row) * HDIM + c8 * 8);
        }
    }
    __syncthreads();

    uint32_t qh[4][4];
    {
        const uint32_t qa = abase + P_OFF +
            2 * ((uint32_t)(w * 16 + (lane & 15)) * ALDT + (lane >> 4) * 8);
        #pragma unroll
        for (int t = 0; t < 4; t++)
            ldmatrix_x4(qh[t], qa + 32 * t);
    }

    float O[8][4];
    #pragma unroll
    for (int j = 0; j < 8; j++)
        #pragma unroll
        for (int e = 0; e < 4; e++) O[j][e] = 0.0f;
    float m0 = -1e30f, m1 = -1e30f, l0 = 0.0f, l1 = 0.0f;

    const int rl0 = w * 16 + (lane >> 2);
    const int c0  = 2 * (lane & 3);
    const uint32_t pa = abase + P_OFF +
        2 * ((uint32_t)(w * 16 + (lane & 15)) * ALDT + (lane >> 4) * 8);

    int cur = 0;
    for (int kt = 0; kt < nkt; kt++) {
        const int kBase = kt * 64;
        CP_WAIT0();
        __syncthreads();
        if (kt + 1 < nkt) {
            stageKV(abase + (uint32_t)((cur ^ 1) * AST_B), (kt + 1) * 64);
            CP_COMMIT();
        }
        const uint32_t uK = abase + (uint32_t)(cur * AST_B);
        const uint32_t uV = uK + KT_B;
        cur ^= 1;

        const int d = kBase - qBase;
        if (d > w * 16 + 15) continue;

        float s[8][4];
        #pragma unroll
        for (int j = 0; j < 8; j++)
            #pragma unroll
            for (int e = 0; e < 4; e++) s[j][e] = 0.0f;

        #pragma unroll
        for (int t = 0; t < 4; t++) {
            #pragma unroll
            for (int jj = 0; jj < 4; jj++) {
                const uint32_t ba = uK + 2 * ((uint32_t)(16 * jj + 8 * (lane >> 4) + (lane & 7)) * ALDT
                                              + 16 * t + 8 * ((lane >> 3) & 1));
                uint32_t kf4[4];
                ldmatrix_x4(kf4, ba);
                mma_f16(s[2 * jj],     qh[t], kf4);
                mma_f16(s[2 * jj + 1], qh[t], kf4 + 2);
            }
        }

        if (kt >= nkt - 2) {
            #pragma unroll
            for (int j = 0; j < 8; j++) {
                #pragma unroll
                for (int e = 0; e < 2; e++) {
                    const int col = 8 * j + c0 + e + d;
                    if (col > rl0)     s[j][e]     = -1e30f;
                    if (col > rl0 + 8) s[j][2 + e] = -1e30f;
                }
            }
        }

        float mt0 = -1e30f, mt1 = -1e30f;
        #pragma unroll
        for (int j = 0; j < 8; j++) {
            mt0 = fmaxf(mt0, fmaxf(s[j][0], s[j][1]));
            mt1 = fmaxf(mt1, fmaxf(s[j][2], s[j][3]));
        }
        mt0 = fmaxf(mt0, __shfl_xor_sync(0xffffffffu, mt0, 1));
        mt0 = fmaxf(mt0, __shfl_xor_sync(0xffffffffu, mt0, 2));
        mt1 = fmaxf(mt1, __shfl_xor_sync(0xffffffffu, mt1, 1));
        mt1 = fmaxf(mt1, __shfl_xor_sync(0xffffffffu, mt1, 2));

        const float mn0 = fmaxf(m0, mt0);
        const float mn1 = fmaxf(m1, mt1);
        const float cr0 = __expf(m0 - mn0);
        const float cr1 = __expf(m1 - mn1);
        m0 = mn0; m1 = mn1;

        float ls0 = 0.0f, ls1 = 0.0f;
        #pragma unroll
        for (int j = 0; j < 8; j++) {
            s[j][0] = __expf(s[j][0] - mn0);
            s[j][1] = __expf(s[j][1] - mn0);
            s[j][2] = __expf(s[j][2] - mn1);
            s[j][3] = __expf(s[j][3] - mn1);
            ls0 += s[j][0] + s[j][1];
            ls1 += s[j][2] + s[j][3];
        }
        ls0 += __shfl_xor_sync(0xffffffffu, ls0, 1);
        ls0 += __shfl_xor_sync(0xffffffffu, ls0, 2);
        ls1 += __shfl_xor_sync(0xffffffffu, ls1, 1);
        ls1 += __shfl_xor_sync(0xffffffffu, ls1, 2);
        l0 = l0 * cr0 + ls0;
        l1 = l1 * cr1 + ls1;
        #pragma unroll
        for (int j = 0; j < 8; j++) {
            O[j][0] *= cr0; O[j][1] *= cr0;
            O[j][2] *= cr1; O[j][3] *= cr1;
        }

        __half* sP = reinterpret_cast<__half*>(asmem + P_OFF);
        #pragma unroll
        for (int j = 0; j < 8; j++) {
            const int col = 8 * j + c0;
            *reinterpret_cast<__half2*>(sP + rl0 * ALDT + col) =
                __halves2half2(__float2half(s[j][0]), __float2half(s[j][1]));
            *reinterpret_cast<__half2*>(sP + (rl0 + 8) * ALDT + col) =
                __halves2half2(__float2half(s[j][2]), __float2half(s[j][3]));
        }
        __syncwarp();

        #pragma unroll
        for (int t = 0; t < 4; t++) {
            uint32_t ph4[4];
            ldmatrix_x4(ph4, pa + 32 * t);
            #pragma unroll
            for (int jj = 0; jj < 4; jj++) {
                const uint32_t va = uV + 2 * ((uint32_t)(16 * jj + 8 * (lane >> 4) + (lane & 7)) * ALDT
                                              + 16 * t + 8 * ((lane >> 3) & 1));
                uint32_t vf4[4];
                ldmatrix_x4(vf4, va);
                mma_f16(O[2 * jj],     ph4, vf4);
                mma_f16(O[2 * jj + 1], ph4, vf4 + 2);
            }
        }
    }

    const float inv0 = 1.0f / l0;
    const float inv1 = 1.0f / l1;
    const int b    = bh >> 4;
    const int head = bh & 15;
    const int r0   = qBase + rl0;
    #pragma unroll
    for (int j = 0; j < 8; j++) {
        const int col = head * HDIM + 8 * j + c0;
        const size_t i0 = (size_t)(b * SEQ + r0) * DMODEL + col;
        const size_t i1 = (size_t)(b * SEQ + r0 + 8) * DMODEL + col;
        *reinterpret_cast<__half2*>(g_cf + i0) =
            __halves2half2(__float2half(O[j][0] * inv0), __float2half(O[j][1] * inv0));
        *reinterpret_cast<__half2*>(g_cf + i1) =
            __halves2half2(__float2half(O[j][2] * inv1), __float2half(O[j][3] * inv1));
    }
}

// ---------------------------------------------------------------------------
// Launch
// ---------------------------------------------------------------------------
extern "C" void kernel_launch(void* const* d_in, const int* in_sizes, int n_in,
                              void* d_out, int out_size)
{
    const float* x  = (const float*)d_in[0];
    const float* wq = (const float*)d_in[1];
    const float* bq = (const float*)d_in[2];
    const float* wk = (const float*)d_in[3];
    const float* bk = (const float*)d_in[4];
    const float* wv = (const float*)d_in[5];
    const float* bv = (const float*)d_in[6];
    const float* wo = (const float*)d_in[7];
    const float* bo = (const float*)d_in[8];
    float* out = (float*)d_out;

    __half *xf, *wf, *qf, *kf, *vf, *cf;
    cudaGetSymbolAddress((void**)&xf, g_xf);
    cudaGetSymbolAddress((void**)&wf, g_wf);
    cudaGetSymbolAddress((void**)&qf, g_qf);
    cudaGetSymbolAddress((void**)&kf, g_kf);
    cudaGetSymbolAddress((void**)&vf, g_vf);
    cudaGetSymbolAddress((void**)&cf, g_cf);

    const size_t NW = (size_t)DMODEL * DMODEL;

    prep_kernel<<<8192, 256>>>(x, wq, wk, wv, wo, xf, wf);

    cudaFuncSetAttribute(mma_gemm_qkv, cudaFuncAttributeMaxDynamicSharedMemorySize, GEMM_SMEM);
    cudaFuncSetAttribute(mma_gemm_out, cudaFuncAttributeMaxDynamicSharedMemorySize, GEMM_SMEM);
    cudaFuncSetAttribute(attn_mma_kernel, cudaFuncAttributeMaxDynamicSharedMemorySize, ATTN_SMEM);

    // Merged Q/K/V projections: grid (24, 32), 256 threads
    dim3 qkvGrid(24, MROWS / 128);
    mma_gemm_qkv<<<qkvGrid, 256, GEMM_SMEM>>>(xf, wf, bq, bk, bv, qf, kf, vf);

    // Tensor-core flash attention: 128-row q tiles
    dim3 attnGrid(SEQ / 128, BATCH * NHEAD);
    attn_mma_kernel<<<attnGrid, 256, ATTN_SMEM>>>();

    // Output projection (plain fp16, fp32 out), 256 threads
    dim3 gemmGrid(DMODEL / 128, MROWS / 128);
    mma_gemm_out<<<gemmGrid, 256, GEMM_SMEM>>>(cf, wf + 3 * NW, bo, out);
}

// round 17
// speedup vs baseline: 1.0669x; 1.0669x over previous
#include <cuda_runtime.h>
#include <cuda_fp16.h>
#include <cstdint>

#define BATCH  2
#define SEQ    2048
#define DMODEL 1024
#define NHEAD  16
#define HDIM   64
#define MROWS  (BATCH * SEQ)       // 4096

// ---------------------------------------------------------------------------
// Scratch (allocation-free rule: __device__ globals)
// ---------------------------------------------------------------------------
__device__ __half g_xf[MROWS * DMODEL];       // x single fp16
__device__ __half g_wf[4][DMODEL * DMODEL];   // wq,wk,wv,wo single fp16
__device__ __half g_qf[MROWS * DMODEL];       // q fp16 [bh][s][hd], scaled 0.125*log2(e)
__device__ __half g_kf[MROWS * DMODEL];       // k single fp16 [bh][s][hd]
__device__ __half g_vf[MROWS * DMODEL];       // v single fp16 TRANSPOSED [bh][hd][s]
__device__ __half g_cf[MROWS * DMODEL];       // ctx single fp16 [b*s][d]

// ---------------------------------------------------------------------------
// Warp-MMA + cp.async helpers (base compute_103 PTX)
// ---------------------------------------------------------------------------
__device__ __forceinline__ uint32_t smem_u32(const void* p) {
    uint32_t a;
    asm("{ .reg .u64 t; cvta.to.shared.u64 t, %1; cvt.u32.u64 %0, t; }"
        : "=r"(a) : "l"(p));
    return a;
}

__device__ __forceinline__ void ldmatrix_x4(uint32_t* r, uint32_t addr) {
    asm volatile("ldmatrix.sync.aligned.m8n8.x4.shared.b16 {%0,%1,%2,%3}, [%4];"
                 : "=r"(r[0]), "=r"(r[1]), "=r"(r[2]), "=r"(r[3]) : "r"(addr));
}

__device__ __forceinline__ void mma_f16(float* c, const uint32_t* a, const uint32_t* b) {
    asm volatile(
        "mma.sync.aligned.m16n8k16.row.col.f32.f16.f16.f32 "
        "{%0,%1,%2,%3}, {%4,%5,%6,%7}, {%8,%9}, {%0,%1,%2,%3};"
        : "+f"(c[0]), "+f"(c[1]), "+f"(c[2]), "+f"(c[3])
        : "r"(a[0]), "r"(a[1]), "r"(a[2]), "r"(a[3]), "r"(b[0]), "r"(b[1]));
}

__device__ __forceinline__ void cp_async16(uint32_t dst, const void* src) {
    asm volatile("cp.async.cg.shared.global [%0], [%1], 16;" :: "r"(dst), "l"(src));
}
#define CP_COMMIT() asm volatile("cp.async.commit_group;" ::: "memory")
#define CP_WAIT0()  asm volatile("cp.async.wait_group 0;" ::: "memory")
#define CP_WAIT1()  asm volatile("cp.async.wait_group 1;" ::: "memory")

// ---------------------------------------------------------------------------
// Prep: convert x and the 4 weight matrices to single fp16.
// ---------------------------------------------------------------------------
__global__ __launch_bounds__(256)
void prep_kernel(const float* __restrict__ x,
                 const float* __restrict__ wq, const float* __restrict__ wk,
                 const float* __restrict__ wv, const float* __restrict__ wo,
                 __half* __restrict__ xf, __half* __restrict__ wf)
{
    const int bid = blockIdx.x;
    const float* src;
    __half* dst;
    int i4;
    if (bid < 4096) {
        src = x;
        dst = xf;
        i4 = (bid * 256 + threadIdx.x) * 4;
    } else {
        const int idx = bid - 4096;
        const int wi  = idx >> 10;
        src = (wi == 0) ? wq : (wi == 1) ? wk : (wi == 2) ? wv : wo;
        dst = wf + (size_t)wi * DMODEL * DMODEL;
        i4 = ((idx & 1023) * 256 + threadIdx.x) * 4;
    }
    float4 f = *reinterpret_cast<const float4*>(src + i4);
    *reinterpret_cast<__half2*>(dst + i4)     = __halves2half2(__float2half(f.x), __float2half(f.y));
    *reinterpret_cast<__half2*>(dst + i4 + 2) = __halves2half2(__float2half(f.z), __float2half(f.w));
}

// ---------------------------------------------------------------------------
// GEMM tiling constants — R15-proven: 256 thr, warp tile 64x32, 3-stage
// fully-unrolled pipeline (prefetch distance 2).
// ---------------------------------------------------------------------------
#define LDT       72
#define TILE_ELEM (128 * LDT)
#define TILE_B    (TILE_ELEM * 2)          // 18432 bytes
#define STAGE_B   (2 * TILE_B)             // 36864 bytes
#define NSTAGE    3
#define GEMM_SMEM (NSTAGE * STAGE_B)       // 110592 bytes
#define NCHUNK    (DMODEL / 64)            // 16

// ---------------------------------------------------------------------------
// Merged QKV GEMM: grid (24, 32); which = blockIdx.x>>3 selects wq/wk/wv.
// which 0 -> q [bh][s][hd] scaled 0.125*log2e; 1 -> k; 2 -> v^T [bh][hd][s]
// ---------------------------------------------------------------------------
__global__ __launch_bounds__(256)
void mma_gemm_qkv(const __half* __restrict__ xf,
                  const __half* __restrict__ wf,
                  const float* __restrict__ bq,
                  const float* __restrict__ bk,
                  const float* __restrict__ bv,
                  __half* __restrict__ qf,
                  __half* __restrict__ kf,
                  __half* __restrict__ vf)
{
    extern __shared__ __align__(16) char smem[];
    const uint32_t sbase = smem_u32(smem);

    const int tid  = threadIdx.x;
    const int wid  = tid >> 5;
    const int lane = tid & 31;
    const int which = blockIdx.x >> 3;
    const int nBase = (blockIdx.x & 7) * 128;
    const int mBase = blockIdx.y * 128;
    const int warp_m = (wid >> 2) * 64;
    const int warp_n = (wid & 3) * 32;

    const size_t NW = (size_t)DMODEL * DMODEL;
    const __half* W = wf + which * NW;
    const float* bias = (which == 0) ? bq : (which == 1) ? bk : bv;
    // q carries 1/8 * log2(e) so attention softmax runs in the log2 domain.
    const float scale = (which == 0) ? 0.125f * 1.44269504089f : 1.0f;

    auto stage = [&](uint32_t sdst, int kc) {
        #pragma unroll
        for (int t = 0; t < 2; t++) {
            const __half* src = (t == 0) ? xf : W;
            const int rb = (t == 0) ? mBase : nBase;
            #pragma unroll
            for (int it = 0; it < 4; it++) {
                const int slot = tid + it * 256;
                const int row  = slot >> 3;
                const int c8   = slot & 7;
                cp_async16(sdst + t * TILE_B + 2 * (uint32_t)(row * LDT + c8 * 8),
                           src + (size_t)(rb + row) * DMODEL + kc + c8 * 8);
            }
        }
    };

    float acc[4][4][4];
    #pragma unroll
    for (int mi = 0; mi < 4; mi++)
        #pragma unroll
        for (int ni = 0; ni < 4; ni++)
            #pragma unroll
            for (int e = 0; e < 4; e++) acc[mi][ni][e] = 0.0f;

    const uint32_t aRow = (uint32_t)(warp_m + (lane & 15)) * LDT + (lane >> 4) * 8;
    const uint32_t bRow = (uint32_t)(warp_n + 8 * (lane >> 4) + (lane & 7)) * LDT
                          + 8 * ((lane >> 3) & 1);

    stage(sbase, 0);
    CP_COMMIT();
    stage(sbase + STAGE_B, 64);
    CP_COMMIT();

    #pragma unroll
    for (int it = 0; it < NCHUNK; it++) {
        if (it < NCHUNK - 1) CP_WAIT1(); else CP_WAIT0();
        __syncthreads();
        if (it + 2 < NCHUNK) {
            stage(sbase + (uint32_t)(((it + 2) % NSTAGE) * STAGE_B), (it + 2) * 64);
            CP_COMMIT();
        }

        const uint32_t sOff = (uint32_t)((it % NSTAGE) * STAGE_B);
        const uint32_t uA = sbase + sOff + 2 * aRow;
        const uint32_t uB = sbase + sOff + TILE_B + 2 * bRow;

        #pragma unroll
        for (int ks = 0; ks < 4; ks++) {
            const uint32_t kOff = 2 * (uint32_t)(ks * 16);
            uint32_t a4[4][4], w4[2][4];
            #pragma unroll
            for (int mi = 0; mi < 4; mi++)
                ldmatrix_x4(a4[mi], uA + kOff + 2 * (uint32_t)(mi * 16) * LDT);
            #pragma unroll
            for (int np = 0; np < 2; np++)
                ldmatrix_x4(w4[np], uB + kOff + 2 * (uint32_t)(np * 16) * LDT);
            #pragma unroll
            for (int mi = 0; mi < 4; mi++)
                #pragma unroll
                for (int ni = 0; ni < 4; ni++)
                    mma_f16(acc[mi][ni], a4[mi], &w4[ni >> 1][2 * (ni & 1)]);
        }
    }

    const int rBase = mBase + warp_m + (lane >> 2);
    const int cBase = nBase + warp_n + (lane & 3) * 2;
    #pragma unroll
    for (int mi = 0; mi < 4; mi++) {
        #pragma unroll
        for (int ni = 0; ni < 4; ni++) {
            #pragma unroll
            for (int half = 0; half < 2; half++) {
                const int m = rBase + mi * 16 + half * 8;
                const int n = cBase + ni * 8;
                const float v0 = (acc[mi][ni][half * 2]     + bias[n])     * scale;
                const float v1 = (acc[mi][ni][half * 2 + 1] + bias[n + 1]) * scale;
                const int b  = m >> 11;
                const int s  = m & 2047;
                const int h  = n >> 6;
                const int hd = n & 63;
                if (which < 2) {
                    const size_t idx = (((size_t)(b * NHEAD + h) * SEQ) + s) * HDIM + hd;
                    __half* dst = (which == 0) ? qf : kf;
                    *reinterpret_cast<__half2*>(dst + idx) =
                        __halves2half2(__float2half(v0), __float2half(v1));
                } else {
                    const size_t idx = (((size_t)(b * NHEAD + h) * HDIM) + hd) * SEQ + s;
                    vf[idx]       = __float2half(v0);
                    vf[idx + SEQ] = __float2half(v1);
                }
            }
        }
    }
}

// ---------------------------------------------------------------------------
// Output-projection GEMM (fp32 out), plain fp16, 3-stage unrolled pipeline.
// ---------------------------------------------------------------------------
__global__ __launch_bounds__(256)
void mma_gemm_out(const __half* __restrict__ A,
                  const __half* __restrict__ W,
                  const float* __restrict__ bias,
                  float* __restrict__ out)
{
    extern __shared__ __align__(16) char smem[];
    const uint32_t sbase = smem_u32(smem);

    const int tid  = threadIdx.x;
    const int wid  = tid >> 5;
    const int lane = tid & 31;
    const int mBase = blockIdx.y * 128;
    const int nBase = blockIdx.x * 128;
    const int warp_m = (wid >> 2) * 64;
    const int warp_n = (wid & 3) * 32;

    auto stage = [&](uint32_t sdst, int kc) {
        #pragma unroll
        for (int t = 0; t < 2; t++) {
            const __half* src = (t == 0) ? A : W;
            const int rb = (t == 0) ? mBase : nBase;
            #pragma unroll
            for (int it = 0; it < 4; it++) {
                const int slot = tid + it * 256;
                const int row  = slot >> 3;
                const int c8   = slot & 7;
                cp_async16(sdst + t * TILE_B + 2 * (uint32_t)(row * LDT + c8 * 8),
                           src + (size_t)(rb + row) * DMODEL + kc + c8 * 8);
            }
        }
    };

    float acc[4][4][4];
    #pragma unroll
    for (int mi = 0; mi < 4; mi++)
        #pragma unroll
        for (int ni = 0; ni < 4; ni++)
            #pragma unroll
            for (int e = 0; e < 4; e++) acc[mi][ni][e] = 0.0f;

    const uint32_t aRow = (uint32_t)(warp_m + (lane & 15)) * LDT + (lane >> 4) * 8;
    const uint32_t bRow = (uint32_t)(warp_n + 8 * (lane >> 4) + (lane & 7)) * LDT
                          + 8 * ((lane >> 3) & 1);

    stage(sbase, 0);
    CP_COMMIT();
    stage(sbase + STAGE_B, 64);
    CP_COMMIT();

    #pragma unroll
    for (int it = 0; it < NCHUNK; it++) {
        if (it < NCHUNK - 1) CP_WAIT1(); else CP_WAIT0();
        __syncthreads();
        if (it + 2 < NCHUNK) {
            stage(sbase + (uint32_t)(((it + 2) % NSTAGE) * STAGE_B), (it + 2) * 64);
            CP_COMMIT();
        }

        const uint32_t sOff = (uint32_t)((it % NSTAGE) * STAGE_B);
        const uint32_t uA = sbase + sOff + 2 * aRow;
        const uint32_t uB = sbase + sOff + TILE_B + 2 * bRow;

        #pragma unroll
        for (int ks = 0; ks < 4; ks++) {
            const uint32_t kOff = 2 * (uint32_t)(ks * 16);
            uint32_t a4[4][4], w4[2][4];
            #pragma unroll
            for (int mi = 0; mi < 4; mi++)
                ldmatrix_x4(a4[mi], uA + kOff + 2 * (uint32_t)(mi * 16) * LDT);
            #pragma unroll
            for (int np = 0; np < 2; np++)
                ldmatrix_x4(w4[np], uB + kOff + 2 * (uint32_t)(np * 16) * LDT);
            #pragma unroll
            for (int mi = 0; mi < 4; mi++)
                #pragma unroll
                for (int ni = 0; ni < 4; ni++)
                    mma_f16(acc[mi][ni], a4[mi], &w4[ni >> 1][2 * (ni & 1)]);
        }
    }

    const int rBase = mBase + warp_m + (lane >> 2);
    const int cBase = nBase + warp_n + (lane & 3) * 2;
    #pragma unroll
    for (int mi = 0; mi < 4; mi++) {
        #pragma unroll
        for (int ni = 0; ni < 4; ni++) {
            #pragma unroll
            for (int half = 0; half < 2; half++) {
                const int m = rBase + mi * 16 + half * 8;
                const int n = cBase + ni * 8;
                out[(size_t)m * DMODEL + n]     = acc[mi][ni][half * 2]     + bias[n];
                out[(size_t)m * DMODEL + n + 1] = acc[mi][ni][half * 2 + 1] + bias[n + 1];
            }
        }
    }
}

// ---------------------------------------------------------------------------
// Tensor-core flash attention (causal), all-single fp16, log2-domain softmax
// (scores pre-scaled by log2e at projection; exp2f everywhere).
// q-tile 128 rows, 256 threads (8 warps), k-tile 64, cp.async double-buffered.
// __launch_bounds__(256,2): 2 CTAs/SM (55KB smem each).
// ---------------------------------------------------------------------------
#define ALDT   72
#define KT_B   9216
#define AST_B  (2 * KT_B)                  // 18432
#define P_OFF  (2 * AST_B)                 // 36864
#define PT_B   (128 * ALDT * 2)            // 18432
#define ATTN_SMEM (P_OFF + PT_B)           // 55296

__global__ __launch_bounds__(256, 2)
void attn_mma_kernel()
{
    extern __shared__ __align__(16) char asmem[];
    const uint32_t abase = smem_u32(asmem);

    const int tid  = threadIdx.x;
    const int w    = tid >> 5;
    const int lane = tid & 31;
    const int qi   = gridDim.x - 1 - blockIdx.x;
    const int bh   = blockIdx.y;
    const int qBase = qi * 128;
    const int nkt  = 2 * qi + 2;
    const size_t hOff = (size_t)bh * SEQ * HDIM;
    const size_t vOff = (size_t)bh * HDIM * SEQ;

    auto stageKV = [&](uint32_t su, int kBase) {
        #pragma unroll
        for (int it = 0; it < 2; it++) {
            const int slot = tid + it * 256;
            const int row = slot >> 3, c8 = slot & 7;
            const uint32_t so = 2 * (uint32_t)(row * ALDT + c8 * 8);
            cp_async16(su + so,        g_kf + hOff + (size_t)(kBase + row) * HDIM + c8 * 8);
            cp_async16(su + KT_B + so, g_vf + vOff + (size_t)row * SEQ + kBase + c8 * 8);
        }
    };

    stageKV(abase, 0);
    CP_COMMIT();

    {
        __half* sP = reinterpret_cast<__half*>(asmem + P_OFF);
        #pragma unroll
        for (int it = 0; it < 4; it++) {
            const int slot = tid + it * 256;
            const int row = slot >> 3, c8 = slot & 7;
            *reinterpret_cast<uint4*>(sP + row * ALDT + c8 * 8) =
                *reinterpret_cast<const uint4*>(g_qf + hOff + (size_t)(qBase + row) * HDIM + c8 * 8);
        }
    }
    __syncthreads();

    uint32_t qh[4][4];
    {
        const uint32_t qa = abase + P_OFF +
            2 * ((uint32_t)(w * 16 + (lane & 15)) * ALDT + (lane >> 4) * 8);
        #pragma unroll
        for (int t = 0; t < 4; t++)
            ldmatrix_x4(qh[t], qa + 32 * t);
    }

    float O[8][4];
    #pragma unroll
    for (int j = 0; j < 8; j++)
        #pragma unroll
        for (int e = 0; e < 4; e++) O[j][e] = 0.0f;
    float m0 = -1e30f, m1 = -1e30f, l0 = 0.0f, l1 = 0.0f;

    const int rl0 = w * 16 + (lane >> 2);
    const int c0  = 2 * (lane & 3);
    const uint32_t pa = abase + P_OFF +
        2 * ((uint32_t)(w * 16 + (lane & 15)) * ALDT + (lane >> 4) * 8);

    int cur = 0;
    for (int kt = 0; kt < nkt; kt++) {
        const int kBase = kt * 64;
        CP_WAIT0();
        __syncthreads();
        if (kt + 1 < nkt) {
            stageKV(abase + (uint32_t)((cur ^ 1) * AST_B), (kt + 1) * 64);
            CP_COMMIT();
        }
        const uint32_t uK = abase + (uint32_t)(cur * AST_B);
        const uint32_t uV = uK + KT_B;
        cur ^= 1;

        const int d = kBase - qBase;
        if (d > w * 16 + 15) continue;

        float s[8][4];
        #pragma unroll
        for (int j = 0; j < 8; j++)
            #pragma unroll
            for (int e = 0; e < 4; e++) s[j][e] = 0.0f;

        #pragma unroll
        for (int t = 0; t < 4; t++) {
            #pragma unroll
            for (int jj = 0; jj < 4; jj++) {
                const uint32_t ba = uK + 2 * ((uint32_t)(16 * jj + 8 * (lane >> 4) + (lane & 7)) * ALDT
                                              + 16 * t + 8 * ((lane >> 3) & 1));
                uint32_t kf4[4];
                ldmatrix_x4(kf4, ba);
                mma_f16(s[2 * jj],     qh[t], kf4);
                mma_f16(s[2 * jj + 1], qh[t], kf4 + 2);
            }
        }

        if (kt >= nkt - 2) {
            #pragma unroll
            for (int j = 0; j < 8; j++) {
                #pragma unroll
                for (int e = 0; e < 2; e++) {
                    const int col = 8 * j + c0 + e + d;
                    if (col > rl0)     s[j][e]     = -1e30f;
                    if (col > rl0 + 8) s[j][2 + e] = -1e30f;
                }
            }
        }

        float mt0 = -1e30f, mt1 = -1e30f;
        #pragma unroll
        for (int j = 0; j < 8; j++) {
            mt0 = fmaxf(mt0, fmaxf(s[j][0], s[j][1]));
            mt1 = fmaxf(mt1, fmaxf(s[j][2], s[j][3]));
        }
        mt0 = fmaxf(mt0, __shfl_xor_sync(0xffffffffu, mt0, 1));
        mt0 = fmaxf(mt0, __shfl_xor_sync(0xffffffffu, mt0, 2));
        mt1 = fmaxf(mt1, __shfl_xor_sync(0xffffffffu, mt1, 1));
        mt1 = fmaxf(mt1, __shfl_xor_sync(0xffffffffu, mt1, 2));

        const float mn0 = fmaxf(m0, mt0);
        const float mn1 = fmaxf(m1, mt1);
        const float cr0 = exp2f(m0 - mn0);
        const float cr1 = exp2f(m1 - mn1);
        m0 = mn0; m1 = mn1;

        float ls0 = 0.0f, ls1 = 0.0f;
        #pragma unroll
        for (int j = 0; j < 8; j++) {
            s[j][0] = exp2f(s[j][0] - mn0);
            s[j][1] = exp2f(s[j][1] - mn0);
            s[j][2] = exp2f(s[j][2] - mn1);
            s[j][3] = exp2f(s[j][3] - mn1);
            ls0 += s[j][0] + s[j][1];
            ls1 += s[j][2] + s[j][3];
        }
        ls0 += __shfl_xor_sync(0xffffffffu, ls0, 1);
        ls0 += __shfl_xor_sync(0xffffffffu, ls0, 2);
        ls1 += __shfl_xor_sync(0xffffffffu, ls1, 1);
        ls1 += __shfl_xor_sync(0xffffffffu, ls1, 2);
        l0 = l0 * cr0 + ls0;
        l1 = l1 * cr1 + ls1;
        #pragma unroll
        for (int j = 0; j < 8; j++) {
            O[j][0] *= cr0; O[j][1] *= cr0;
            O[j][2] *= cr1; O[j][3] *= cr1;
        }

        __half* sP = reinterpret_cast<__half*>(asmem + P_OFF);
        #pragma unroll
        for (int j = 0; j < 8; j++) {
            const int col = 8 * j + c0;
            *reinterpret_cast<__half2*>(sP + rl0 * ALDT + col) =
                __halves2half2(__float2half(s[j][0]), __float2half(s[j][1]));
            *reinterpret_cast<__half2*>(sP + (rl0 + 8) * ALDT + col) =
                __halves2half2(__float2half(s[j][2]), __float2half(s[j][3]));
        }
        __syncwarp();

        #pragma unroll
        for (int t = 0; t < 4; t++) {
            uint32_t ph4[4];
            ldmatrix_x4(ph4, pa + 32 * t);
            #pragma unroll
            for (int jj = 0; jj < 4; jj++) {
                const uint32_t va = uV + 2 * ((uint32_t)(16 * jj + 8 * (lane >> 4) + (lane & 7)) * ALDT
                                              + 16 * t + 8 * ((lane >> 3) & 1));
                uint32_t vf4[4];
                ldmatrix_x4(vf4, va);
                mma_f16(O[2 * jj],     ph4, vf4);
                mma_f16(O[2 * jj + 1], ph4, vf4 + 2);
            }
        }
    }

    const float inv0 = 1.0f / l0;
    const float inv1 = 1.0f / l1;
    const int b    = bh >> 4;
    const int head = bh & 15;
    const int r0   = qBase + rl0;
    #pragma unroll
    for (int j = 0; j < 8; j++) {
        const int col = head * HDIM + 8 * j + c0;
        const size_t i0 = (size_t)(b * SEQ + r0) * DMODEL + col;
        const size_t i1 = (size_t)(b * SEQ + r0 + 8) * DMODEL + col;
        *reinterpret_cast<__half2*>(g_cf + i0) =
            __halves2half2(__float2half(O[j][0] * inv0), __float2half(O[j][1] * inv0));
        *reinterpret_cast<__half2*>(g_cf + i1) =
            __halves2half2(__float2half(O[j][2] * inv1), __float2half(O[j][3] * inv1));
    }
}

// ---------------------------------------------------------------------------
// Launch
// ---------------------------------------------------------------------------
extern "C" void kernel_launch(void* const* d_in, const int* in_sizes, int n_in,
                              void* d_out, int out_size)
{
    const float* x  = (const float*)d_in[0];
    const float* wq = (const float*)d_in[1];
    const float* bq = (const float*)d_in[2];
    const float* wk = (const float*)d_in[3];
    const float* bk = (const float*)d_in[4];
    const float* wv = (const float*)d_in[5];
    const float* bv = (const float*)d_in[6];
    const float* wo = (const float*)d_in[7];
    const float* bo = (const float*)d_in[8];
    float* out = (float*)d_out;

    __half *xf, *wf, *qf, *kf, *vf, *cf;
    cudaGetSymbolAddress((void**)&xf, g_xf);
    cudaGetSymbolAddress((void**)&wf, g_wf);
    cudaGetSymbolAddress((void**)&qf, g_qf);
    cudaGetSymbolAddress((void**)&kf, g_kf);
    cudaGetSymbolAddress((void**)&vf, g_vf);
    cudaGetSymbolAddress((void**)&cf, g_cf);

    const size_t NW = (size_t)DMODEL * DMODEL;

    prep_kernel<<<8192, 256>>>(x, wq, wk, wv, wo, xf, wf);

    cudaFuncSetAttribute(mma_gemm_qkv, cudaFuncAttributeMaxDynamicSharedMemorySize, GEMM_SMEM);
    cudaFuncSetAttribute(mma_gemm_out, cudaFuncAttributeMaxDynamicSharedMemorySize, GEMM_SMEM);
    cudaFuncSetAttribute(attn_mma_kernel, cudaFuncAttributeMaxDynamicSharedMemorySize, ATTN_SMEM);

    // Merged Q/K/V projections: grid (24, 32), 256 threads
    dim3 qkvGrid(24, MROWS / 128);
    mma_gemm_qkv<<<qkvGrid, 256, GEMM_SMEM>>>(xf, wf, bq, bk, bv, qf, kf, vf);

    // Tensor-core flash attention: 128-row q tiles
    dim3 attnGrid(SEQ / 128, BATCH * NHEAD);
    attn_mma_kernel<<<attnGrid, 256, ATTN_SMEM>>>();

    // Output projection (plain fp16, fp32 out), 256 threads
    dim3 gemmGrid(DMODEL / 128, MROWS / 128);
    mma_gemm_out<<<gemmGrid, 256, GEMM_SMEM>>>(cf, wf + 3 * NW, bo, out);
}